// round 2
// baseline (speedup 1.0000x reference)
#include <cuda_runtime.h>
#include <cstdint>

#define M_DIM 4096
#define K_DIM 4096
#define N_DIM 4096
#define NV4_N 2048
#define FP8_N 1024

// Pre-dequantized, permutation-folded weights: W_perm[j][k] = dequant(W_grouped[inv_perm[j]][k])
__device__ float g_W[(size_t)N_DIM * K_DIM];   // 64 MB scratch (__device__ global: allowed)
__device__ int   g_perm[N_DIM];                // canonical int32 permutation

__constant__ float c_code[16] = {0.f, 0.5f, 1.f, 1.5f, 2.f, 3.f, 4.f, 6.f,
                                 -0.f, -0.5f, -1.f, -1.5f, -2.f, -3.f, -4.f, -6.f};

// Detect whether inv_perm is int64 or int32 (JAX x64-disabled silently downcasts)
// and write a canonical int32 copy. Single block.
__global__ void perm_canon_kernel(const void* __restrict__ perm_raw)
{
    __shared__ int s_bad;
    const int tid = threadIdx.x;
    if (tid == 0) s_bad = 0;
    __syncthreads();

    // Probe first 2048 int64 slots = 16KB: safe whether the buffer is
    // 4096*int32 (16KB) or 4096*int64 (32KB).
    const long long* p64 = (const long long*)perm_raw;
    for (int i = tid; i < 2048; i += blockDim.x) {
        long long v = p64[i];
        if (v < 0 || v >= N_DIM) atomicOr(&s_bad, 1);
    }
    __syncthreads();

    if (s_bad) {   // int32 data
        const int* p32 = (const int*)perm_raw;
        for (int i = tid; i < N_DIM; i += blockDim.x) g_perm[i] = p32[i];
    } else {       // genuine int64
        for (int i = tid; i < N_DIM; i += blockDim.x) g_perm[i] = (int)p64[i];
    }
}

// One block per output channel j. Folds inv_perm, nvfp4 scales, global scale, fp8 scale.
__global__ void dequant_kernel(const int* __restrict__ nvfp4_idx,
                               const float* __restrict__ nvfp4_scales,
                               const float* __restrict__ gscale_p,
                               const float* __restrict__ w_fp8,
                               const float* __restrict__ fp8_scale_p,
                               const float* __restrict__ w_fp16)
{
    const int j = blockIdx.x;
    const int g = g_perm[j];
    float* __restrict__ dst = &g_W[(size_t)j * K_DIM];
    const int tid = threadIdx.x;

    if (g < NV4_N) {
        const float gs = gscale_p[0];
        const int* __restrict__ idx = nvfp4_idx + (size_t)g * K_DIM;
        const float* __restrict__ sc = nvfp4_scales + (size_t)g * (K_DIM / 16);
        for (int k = tid * 16; k < K_DIM; k += blockDim.x * 16) {
            const float s = sc[k >> 4] * gs;
            #pragma unroll
            for (int c = 0; c < 16; c += 4) {
                int4 iv = *(const int4*)&idx[k + c];
                float4 v;
                v.x = c_code[iv.x & 15] * s;
                v.y = c_code[iv.y & 15] * s;
                v.z = c_code[iv.z & 15] * s;
                v.w = c_code[iv.w & 15] * s;
                *(float4*)&dst[k + c] = v;
            }
        }
    } else if (g < NV4_N + FP8_N) {
        const float fs = fp8_scale_p[0];
        const float* __restrict__ w = w_fp8 + (size_t)(g - NV4_N) * K_DIM;
        for (int k = tid * 4; k < K_DIM; k += blockDim.x * 4) {
            float4 v = *(const float4*)&w[k];
            v.x *= fs; v.y *= fs; v.z *= fs; v.w *= fs;
            *(float4*)&dst[k] = v;
        }
    } else {
        const float* __restrict__ w = w_fp16 + (size_t)(g - NV4_N - FP8_N) * K_DIM;
        for (int k = tid * 4; k < K_DIM; k += blockDim.x * 4)
            *(float4*)&dst[k] = *(const float4*)&w[k];
    }
}

// Classic 128x128x16 register-blocked SGEMM. C[m][n] = sum_k X[m][k]*W[n][k] + bias[n].
#define BM 128
#define BN 128
#define BK 16

__global__ __launch_bounds__(256, 2)
void gemm_kernel(const float* __restrict__ X,
                 const float* __restrict__ bias,
                 float* __restrict__ out)
{
    __shared__ float As[BK][BM];
    __shared__ float Bs[BK][BN];

    const int tid = threadIdx.x;
    const int m0 = blockIdx.y * BM;
    const int n0 = blockIdx.x * BN;
    const int tm = tid >> 4;        // 0..15
    const int tn = tid & 15;        // 0..15

    const int lrow = tid >> 2;      // 0..63
    const int lk   = (tid & 3) * 4; // 0,4,8,12

    const float* Aptr = X   + (size_t)(m0 + lrow) * K_DIM + lk;
    const float* Bptr = g_W + (size_t)(n0 + lrow) * K_DIM + lk;

    float acc[8][8] = {};

    for (int k0 = 0; k0 < K_DIM; k0 += BK) {
        float4 a0 = *(const float4*)(Aptr);
        float4 a1 = *(const float4*)(Aptr + (size_t)64 * K_DIM);
        float4 b0 = *(const float4*)(Bptr);
        float4 b1 = *(const float4*)(Bptr + (size_t)64 * K_DIM);
        __syncthreads();  // protect previous iter's smem reads
        As[lk + 0][lrow] = a0.x; As[lk + 1][lrow] = a0.y;
        As[lk + 2][lrow] = a0.z; As[lk + 3][lrow] = a0.w;
        As[lk + 0][lrow + 64] = a1.x; As[lk + 1][lrow + 64] = a1.y;
        As[lk + 2][lrow + 64] = a1.z; As[lk + 3][lrow + 64] = a1.w;
        Bs[lk + 0][lrow] = b0.x; Bs[lk + 1][lrow] = b0.y;
        Bs[lk + 2][lrow] = b0.z; Bs[lk + 3][lrow] = b0.w;
        Bs[lk + 0][lrow + 64] = b1.x; Bs[lk + 1][lrow + 64] = b1.y;
        Bs[lk + 2][lrow + 64] = b1.z; Bs[lk + 3][lrow + 64] = b1.w;
        __syncthreads();

        #pragma unroll
        for (int k = 0; k < BK; k++) {
            float4 ra0 = *(const float4*)&As[k][tm * 8];
            float4 ra1 = *(const float4*)&As[k][tm * 8 + 4];
            float4 rb0 = *(const float4*)&Bs[k][tn * 8];
            float4 rb1 = *(const float4*)&Bs[k][tn * 8 + 4];
            float a[8] = {ra0.x, ra0.y, ra0.z, ra0.w, ra1.x, ra1.y, ra1.z, ra1.w};
            float b[8] = {rb0.x, rb0.y, rb0.z, rb0.w, rb1.x, rb1.y, rb1.z, rb1.w};
            #pragma unroll
            for (int i = 0; i < 8; i++)
                #pragma unroll
                for (int jj = 0; jj < 8; jj++)
                    acc[i][jj] += a[i] * b[jj];
        }
        Aptr += BK;
        Bptr += BK;
    }

    float bv[8];
    #pragma unroll
    for (int jj = 0; jj < 8; jj++) bv[jj] = bias[n0 + tn * 8 + jj];

    #pragma unroll
    for (int i = 0; i < 8; i++) {
        const int m = m0 + tm * 8 + i;
        float* orow = out + (size_t)m * N_DIM + n0 + tn * 8;
        float4 v0, v1;
        v0.x = acc[i][0] + bv[0]; v0.y = acc[i][1] + bv[1];
        v0.z = acc[i][2] + bv[2]; v0.w = acc[i][3] + bv[3];
        v1.x = acc[i][4] + bv[4]; v1.y = acc[i][5] + bv[5];
        v1.z = acc[i][6] + bv[6]; v1.w = acc[i][7] + bv[7];
        *(float4*)(orow)     = v0;
        *(float4*)(orow + 4) = v1;
    }
}

extern "C" void kernel_launch(void* const* d_in, const int* in_sizes, int n_in,
                              void* d_out, int out_size)
{
    const float* x            = (const float*)d_in[0];
    const int*   nvfp4_idx    = (const int*)d_in[1];
    const float* nvfp4_scales = (const float*)d_in[2];
    const float* nvfp4_gscale = (const float*)d_in[3];
    const float* w_fp8        = (const float*)d_in[4];
    const float* fp8_scale    = (const float*)d_in[5];
    const float* w_fp16       = (const float*)d_in[6];
    const float* bias         = (const float*)d_in[7];
    const void*  inv_perm     = (const void*)d_in[8];
    float*       out          = (float*)d_out;

    perm_canon_kernel<<<1, 256>>>(inv_perm);

    dequant_kernel<<<N_DIM, 256>>>(nvfp4_idx, nvfp4_scales, nvfp4_gscale,
                                   w_fp8, fp8_scale, w_fp16);

    dim3 grid(N_DIM / BN, M_DIM / BM);
    gemm_kernel<<<grid, 256>>>(x, bias, out);
}

// round 4
// speedup vs baseline: 5.2093x; 5.2093x over previous
#include <cuda_runtime.h>
#include <cuda_fp16.h>
#include <cstdint>

#define M_DIM 4096
#define K_DIM 4096
#define N_DIM 4096
#define NV4_N 2048
#define FP8_N 1024

#define BM 128
#define BN 128
#define BK 64
#define STAGES 3
#define NITER (K_DIM / BK)     // 64

// ---- scratch (device globals: allowed) ----
__device__ __half g_Wh[(size_t)N_DIM * K_DIM];   // 32 MB dequantized+permuted W (fp16)
__device__ __half g_Xh[(size_t)M_DIM * K_DIM];   // 32 MB fp16 X
__device__ int    g_perm[N_DIM];

__constant__ float c_code[16] = {0.f, 0.5f, 1.f, 1.5f, 2.f, 3.f, 4.f, 6.f,
                                 -0.f, -0.5f, -1.f, -1.5f, -2.f, -3.f, -4.f, -6.f};

// ================= helpers =================
__device__ __forceinline__ uint32_t smem_u32(const void* p) {
    uint32_t a;
    asm("{ .reg .u64 t; cvta.to.shared.u64 t, %1; cvt.u32.u64 %0, t; }" : "=r"(a) : "l"(p));
    return a;
}
#define CP_ASYNC16(dst, src) \
    asm volatile("cp.async.cg.shared.global [%0], [%1], 16;" :: "r"(dst), "l"(src) : "memory")
#define CP_COMMIT() asm volatile("cp.async.commit_group;" ::: "memory")
#define CP_WAIT1()  asm volatile("cp.async.wait_group 1;" ::: "memory")

#define LDSM_X4(r0, r1, r2, r3, addr) \
    asm volatile("ldmatrix.sync.aligned.m8n8.x4.shared.b16 {%0,%1,%2,%3}, [%4];" \
                 : "=r"(r0), "=r"(r1), "=r"(r2), "=r"(r3) : "r"(addr))

#define MMA16816(c, a, b) \
    asm volatile("mma.sync.aligned.m16n8k16.row.col.f32.f16.f16.f32 " \
                 "{%0,%1,%2,%3}, {%4,%5,%6,%7}, {%8,%9}, {%0,%1,%2,%3};" \
                 : "+f"((c)[0]), "+f"((c)[1]), "+f"((c)[2]), "+f"((c)[3]) \
                 : "r"((a)[0]), "r"((a)[1]), "r"((a)[2]), "r"((a)[3]), \
                   "r"((b)[0]), "r"((b)[1]))

#define SW128(off) ((off) ^ (((off) >> 3) & 0x70))

// SMEM layout (dynamic): A stages then B stages, 16KB each (128 rows x 128B)
#define SM_A(s)  ((s) * 16384)
#define SM_B(s)  (49152 + (s) * 16384)
#define SMEM_TOTAL 98304

// ================= pre-kernels =================
__global__ void perm_canon_kernel(const void* __restrict__ perm_raw)
{
    __shared__ int s_bad;
    const int tid = threadIdx.x;
    if (tid == 0) s_bad = 0;
    __syncthreads();
    const long long* p64 = (const long long*)perm_raw;
    for (int i = tid; i < 2048; i += blockDim.x) {
        long long v = p64[i];
        if (v < 0 || v >= N_DIM) atomicOr(&s_bad, 1);
    }
    __syncthreads();
    if (s_bad) { const int* p32 = (const int*)perm_raw;
        for (int i = tid; i < N_DIM; i += blockDim.x) g_perm[i] = p32[i];
    } else {
        for (int i = tid; i < N_DIM; i += blockDim.x) g_perm[i] = (int)p64[i];
    }
}

__global__ void convert_x_kernel(const float* __restrict__ X)
{
    size_t i = ((size_t)blockIdx.x * blockDim.x + threadIdx.x) * 8;
    float4 a = *(const float4*)(X + i);
    float4 b = *(const float4*)(X + i + 4);
    __half2 h[4];
    h[0] = __floats2half2_rn(a.x, a.y);
    h[1] = __floats2half2_rn(a.z, a.w);
    h[2] = __floats2half2_rn(b.x, b.y);
    h[3] = __floats2half2_rn(b.z, b.w);
    *(uint4*)(g_Xh + i) = *(uint4*)h;
}

__global__ void dequant_kernel(const int* __restrict__ nvfp4_idx,
                               const float* __restrict__ nvfp4_scales,
                               const float* __restrict__ gscale_p,
                               const float* __restrict__ w_fp8,
                               const float* __restrict__ fp8_scale_p,
                               const float* __restrict__ w_fp16)
{
    const int j = blockIdx.x;
    const int g = g_perm[j];
    __half* __restrict__ dst = &g_Wh[(size_t)j * K_DIM];
    const int tid = threadIdx.x;

    if (g < NV4_N) {
        const float gs = gscale_p[0];
        const int* __restrict__ idx = nvfp4_idx + (size_t)g * K_DIM;
        const float* __restrict__ sc = nvfp4_scales + (size_t)g * (K_DIM / 16);
        const int k = tid * 16;   // 256 threads x 16 = 4096
        const float s = sc[k >> 4] * gs;
        #pragma unroll
        for (int c = 0; c < 16; c += 8) {
            int4 i0 = *(const int4*)&idx[k + c];
            int4 i1 = *(const int4*)&idx[k + c + 4];
            __half2 h[4];
            h[0] = __floats2half2_rn(c_code[i0.x & 15] * s, c_code[i0.y & 15] * s);
            h[1] = __floats2half2_rn(c_code[i0.z & 15] * s, c_code[i0.w & 15] * s);
            h[2] = __floats2half2_rn(c_code[i1.x & 15] * s, c_code[i1.y & 15] * s);
            h[3] = __floats2half2_rn(c_code[i1.z & 15] * s, c_code[i1.w & 15] * s);
            *(uint4*)&dst[k + c] = *(uint4*)h;
        }
    } else {
        const bool is8 = (g < NV4_N + FP8_N);
        const float fs = is8 ? fp8_scale_p[0] : 1.f;
        const float* __restrict__ w = is8 ? (w_fp8 + (size_t)(g - NV4_N) * K_DIM)
                                          : (w_fp16 + (size_t)(g - NV4_N - FP8_N) * K_DIM);
        for (int k = tid * 8; k < K_DIM; k += blockDim.x * 8) {
            float4 a = *(const float4*)&w[k];
            float4 b = *(const float4*)&w[k + 4];
            __half2 h[4];
            h[0] = __floats2half2_rn(a.x * fs, a.y * fs);
            h[1] = __floats2half2_rn(a.z * fs, a.w * fs);
            h[2] = __floats2half2_rn(b.x * fs, b.y * fs);
            h[3] = __floats2half2_rn(b.z * fs, b.w * fs);
            *(uint4*)&dst[k] = *(uint4*)h;
        }
    }
}

// ================= HMMA GEMM =================
__device__ __forceinline__ void load_stage(uint32_t smem_base, int s, int it, int m0, int n0)
{
    const int tid = threadIdx.x;
    const int k0 = it * BK;
    const uint32_t a_base = smem_base + SM_A(s);
    const uint32_t b_base = smem_base + SM_B(s);
    const int row = tid >> 1;            // 0..127
    const int c16 = (tid & 1) * 4;       // 0 or 4 (of 8 chunks per 128B row)
    // A: 128 rows x 8 chunks; each thread does 4 consecutive chunks of one row
    {
        const __half* src = g_Xh + (size_t)(m0 + row) * K_DIM + k0 + c16 * 8;
        #pragma unroll
        for (int c = 0; c < 4; c++) {
            uint32_t off = row * 128 + (c16 + c) * 16;
            CP_ASYNC16(a_base + SW128(off), src + c * 8);
        }
    }
    {
        const __half* src = g_Wh + (size_t)(n0 + row) * K_DIM + k0 + c16 * 8;
        #pragma unroll
        for (int c = 0; c < 4; c++) {
            uint32_t off = row * 128 + (c16 + c) * 16;
            CP_ASYNC16(b_base + SW128(off), src + c * 8);
        }
    }
}

__global__ __launch_bounds__(256, 1)
void gemm_hmma_kernel(const float* __restrict__ bias, float* __restrict__ out)
{
    extern __shared__ char smem[];
    const uint32_t smem_base = smem_u32(smem);
    const int tid  = threadIdx.x;
    const int wid  = tid >> 5, lane = tid & 31;
    const int wm   = wid & 1;            // 2 warps along M
    const int wn   = wid >> 1;           // 4 warps along N
    const int m0   = blockIdx.y * BM;
    const int n0   = blockIdx.x * BN;

    float acc[4][4][4] = {};             // [m-tile][n-tile][frag]

    // precomputed ldmatrix source offsets (swizzled) — per-lane constants
    // A: row = wm*64 + mt*16 + (lane&15), half-col chunk = (lane>>4)*8 halves
    const int a_row = wm * 64 + (lane & 15);
    const int a_kh  = (lane >> 4) * 8;
    // B x4 covers two n8-tiles: lanes 0-15 -> nt even, 16-31 -> nt odd;
    // within: lanes 0-7 k-lo, 8-15 k-hi
    const int b_nt_off = (lane >> 4);          // 0 or 1
    const int b_row = wn * 32 + b_nt_off * 8 + (lane & 7);
    const int b_kh  = ((lane >> 3) & 1) * 8;

    // prefetch stages 0,1
    #pragma unroll
    for (int s = 0; s < STAGES - 1; s++) { load_stage(smem_base, s, s, m0, n0); CP_COMMIT(); }

    for (int it = 0; it < NITER; it++) {
        const int s = it % STAGES;
        CP_WAIT1();
        __syncthreads();

        const int nxt = it + STAGES - 1;
        if (nxt < NITER) { load_stage(smem_base, nxt % STAGES, nxt, m0, n0); CP_COMMIT(); }

        const uint32_t a_base = smem_base + SM_A(s);
        const uint32_t b_base = smem_base + SM_B(s);

        #pragma unroll
        for (int kk = 0; kk < 4; kk++) {          // 4 x k16 per BK=64
            const int k0 = kk * 16;
            uint32_t af[4][4];
            #pragma unroll
            for (int mt = 0; mt < 4; mt++) {
                uint32_t off = (mt * 16 + a_row) * 128 + (k0 + a_kh) * 2;
                LDSM_X4(af[mt][0], af[mt][1], af[mt][2], af[mt][3],
                        a_base + SW128(off));
            }
            uint32_t bf[4][2];
            #pragma unroll
            for (int p = 0; p < 2; p++) {          // nt pair {2p, 2p+1}
                uint32_t off = (p * 16 + b_row) * 128 + (k0 + b_kh) * 2;
                LDSM_X4(bf[2 * p][0], bf[2 * p][1], bf[2 * p + 1][0], bf[2 * p + 1][1],
                        b_base + SW128(off));
            }
            #pragma unroll
            for (int mt = 0; mt < 4; mt++)
                #pragma unroll
                for (int nt = 0; nt < 4; nt++)
                    MMA16816(acc[mt][nt], af[mt], bf[nt]);
        }
    }

    // epilogue: c0,c1 -> row lane/4, cols 2(lane&3)+{0,1}; c2,c3 -> row+8
    const int er = lane >> 2;
    const int ec = (lane & 3) * 2;
    #pragma unroll
    for (int nt = 0; nt < 4; nt++) {
        const int n = n0 + wn * 32 + nt * 8 + ec;
        const float2 bv = *(const float2*)(bias + n);
        #pragma unroll
        for (int mt = 0; mt < 4; mt++) {
            const int m = m0 + wm * 64 + mt * 16 + er;
            float2 v0 = { acc[mt][nt][0] + bv.x, acc[mt][nt][1] + bv.y };
            float2 v1 = { acc[mt][nt][2] + bv.x, acc[mt][nt][3] + bv.y };
            *(float2*)(out + (size_t)m * N_DIM + n)       = v0;
            *(float2*)(out + (size_t)(m + 8) * N_DIM + n) = v1;
        }
    }
}

// ================= launch =================
extern "C" void kernel_launch(void* const* d_in, const int* in_sizes, int n_in,
                              void* d_out, int out_size)
{
    const float* x            = (const float*)d_in[0];
    const int*   nvfp4_idx    = (const int*)d_in[1];
    const float* nvfp4_scales = (const float*)d_in[2];
    const float* nvfp4_gscale = (const float*)d_in[3];
    const float* w_fp8        = (const float*)d_in[4];
    const float* fp8_scale    = (const float*)d_in[5];
    const float* w_fp16       = (const float*)d_in[6];
    const float* bias         = (const float*)d_in[7];
    const void*  inv_perm     = (const void*)d_in[8];
    float*       out          = (float*)d_out;

    cudaFuncSetAttribute(gemm_hmma_kernel, cudaFuncAttributeMaxDynamicSharedMemorySize, SMEM_TOTAL);

    perm_canon_kernel<<<1, 256>>>(inv_perm);
    convert_x_kernel<<<(M_DIM * (size_t)K_DIM) / (256 * 8), 256>>>(x);
    dequant_kernel<<<N_DIM, 256>>>(nvfp4_idx, nvfp4_scales, nvfp4_gscale,
                                   w_fp8, fp8_scale, w_fp16);

    dim3 grid(N_DIM / BN, M_DIM / BM);   // (32, 32)
    gemm_hmma_kernel<<<grid, 256, SMEM_TOTAL>>>(bias, out);
}

// round 5
// speedup vs baseline: 7.2821x; 1.3979x over previous
#include <cuda_runtime.h>
#include <cuda_fp16.h>
#include <cstdint>

#define M_DIM 4096
#define K_DIM 4096
#define N_DIM 4096
#define NV4_N 2048
#define FP8_N 1024

#define BM 128
#define BN 256
#define BK 64
#define STAGES 3
#define NITER (K_DIM / BK)     // 64
#define NTHREADS 512

// ---- scratch (device globals: allowed) ----
__device__ __half g_Wh[(size_t)N_DIM * K_DIM];   // 32 MB dequantized+permuted W (fp16)
__device__ __half g_Xh[(size_t)M_DIM * K_DIM];   // 32 MB fp16 X
__device__ int    g_perm[N_DIM];

__constant__ float c_code[16] = {0.f, 0.5f, 1.f, 1.5f, 2.f, 3.f, 4.f, 6.f,
                                 -0.f, -0.5f, -1.f, -1.5f, -2.f, -3.f, -4.f, -6.f};

// ================= helpers =================
__device__ __forceinline__ uint32_t smem_u32(const void* p) {
    uint32_t a;
    asm("{ .reg .u64 t; cvta.to.shared.u64 t, %1; cvt.u32.u64 %0, t; }" : "=r"(a) : "l"(p));
    return a;
}
#define CP_ASYNC16(dst, src) \
    asm volatile("cp.async.cg.shared.global [%0], [%1], 16;" :: "r"(dst), "l"(src) : "memory")
#define CP_COMMIT() asm volatile("cp.async.commit_group;" ::: "memory")
#define CP_WAIT1()  asm volatile("cp.async.wait_group 1;" ::: "memory")

#define LDSM_X4(r0, r1, r2, r3, addr) \
    asm volatile("ldmatrix.sync.aligned.m8n8.x4.shared.b16 {%0,%1,%2,%3}, [%4];" \
                 : "=r"(r0), "=r"(r1), "=r"(r2), "=r"(r3) : "r"(addr))

#define MMA16816(c, a, b) \
    asm volatile("mma.sync.aligned.m16n8k16.row.col.f32.f16.f16.f32 " \
                 "{%0,%1,%2,%3}, {%4,%5,%6,%7}, {%8,%9}, {%0,%1,%2,%3};" \
                 : "+f"((c)[0]), "+f"((c)[1]), "+f"((c)[2]), "+f"((c)[3]) \
                 : "r"((a)[0]), "r"((a)[1]), "r"((a)[2]), "r"((a)[3]), \
                   "r"((b)[0]), "r"((b)[1]))

#define SW128(off) ((off) ^ (((off) >> 3) & 0x70))

// SMEM layout: A stages 16KB each (128 rows x 128B), B stages 32KB each (256 rows x 128B)
#define SM_A(s)  ((s) * 16384)
#define SM_B(s)  (49152 + (s) * 32768)
#define SMEM_TOTAL (49152 + STAGES * 32768)   // 147456

// ================= pre-kernels =================
__global__ void perm_canon_kernel(const void* __restrict__ perm_raw)
{
    __shared__ int s_bad;
    const int tid = threadIdx.x;
    if (tid == 0) s_bad = 0;
    __syncthreads();
    const long long* p64 = (const long long*)perm_raw;
    for (int i = tid; i < 2048; i += blockDim.x) {
        long long v = p64[i];
        if (v < 0 || v >= N_DIM) atomicOr(&s_bad, 1);
    }
    __syncthreads();
    if (s_bad) { const int* p32 = (const int*)perm_raw;
        for (int i = tid; i < N_DIM; i += blockDim.x) g_perm[i] = p32[i];
    } else {
        for (int i = tid; i < N_DIM; i += blockDim.x) g_perm[i] = (int)p64[i];
    }
}

__global__ void convert_x_kernel(const float* __restrict__ X)
{
    size_t i = ((size_t)blockIdx.x * blockDim.x + threadIdx.x) * 8;
    float4 a = *(const float4*)(X + i);
    float4 b = *(const float4*)(X + i + 4);
    __half2 h[4];
    h[0] = __floats2half2_rn(a.x, a.y);
    h[1] = __floats2half2_rn(a.z, a.w);
    h[2] = __floats2half2_rn(b.x, b.y);
    h[3] = __floats2half2_rn(b.z, b.w);
    *(uint4*)(g_Xh + i) = *(uint4*)h;
}

__global__ void dequant_kernel(const int* __restrict__ nvfp4_idx,
                               const float* __restrict__ nvfp4_scales,
                               const float* __restrict__ gscale_p,
                               const float* __restrict__ w_fp8,
                               const float* __restrict__ fp8_scale_p,
                               const float* __restrict__ w_fp16)
{
    const int j = blockIdx.x;
    const int g = g_perm[j];
    __half* __restrict__ dst = &g_Wh[(size_t)j * K_DIM];
    const int tid = threadIdx.x;

    if (g < NV4_N) {
        const float gs = gscale_p[0];
        const int* __restrict__ idx = nvfp4_idx + (size_t)g * K_DIM;
        const float* __restrict__ sc = nvfp4_scales + (size_t)g * (K_DIM / 16);
        const int k = tid * 16;   // 256 threads x 16 = 4096
        const float s = sc[k >> 4] * gs;
        #pragma unroll
        for (int c = 0; c < 16; c += 8) {
            int4 i0 = *(const int4*)&idx[k + c];
            int4 i1 = *(const int4*)&idx[k + c + 4];
            __half2 h[4];
            h[0] = __floats2half2_rn(c_code[i0.x & 15] * s, c_code[i0.y & 15] * s);
            h[1] = __floats2half2_rn(c_code[i0.z & 15] * s, c_code[i0.w & 15] * s);
            h[2] = __floats2half2_rn(c_code[i1.x & 15] * s, c_code[i1.y & 15] * s);
            h[3] = __floats2half2_rn(c_code[i1.z & 15] * s, c_code[i1.w & 15] * s);
            *(uint4*)&dst[k + c] = *(uint4*)h;
        }
    } else {
        const bool is8 = (g < NV4_N + FP8_N);
        const float fs = is8 ? fp8_scale_p[0] : 1.f;
        const float* __restrict__ w = is8 ? (w_fp8 + (size_t)(g - NV4_N) * K_DIM)
                                          : (w_fp16 + (size_t)(g - NV4_N - FP8_N) * K_DIM);
        for (int k = tid * 8; k < K_DIM; k += blockDim.x * 8) {
            float4 a = *(const float4*)&w[k];
            float4 b = *(const float4*)&w[k + 4];
            __half2 h[4];
            h[0] = __floats2half2_rn(a.x * fs, a.y * fs);
            h[1] = __floats2half2_rn(a.z * fs, a.w * fs);
            h[2] = __floats2half2_rn(b.x * fs, b.y * fs);
            h[3] = __floats2half2_rn(b.z * fs, b.w * fs);
            *(uint4*)&dst[k] = *(uint4*)h;
        }
    }
}

// ================= HMMA GEMM (128x256, 512 threads, 16 warps 4x4) =================
__device__ __forceinline__ void load_stage(uint32_t smem_base, int s, int it, int m0, int n0)
{
    const int tid = threadIdx.x;
    const int k0 = it * BK;
    const uint32_t a_base = smem_base + SM_A(s);
    const uint32_t b_base = smem_base + SM_B(s);
    // A: 128 rows x 8 x 16B = 1024 granules, 2 per thread
    #pragma unroll
    for (int i = 0; i < 2; i++) {
        int gr = tid + i * NTHREADS;
        int row = gr >> 3, c16 = gr & 7;
        const __half* src = g_Xh + (size_t)(m0 + row) * K_DIM + k0 + c16 * 8;
        uint32_t off = row * 128 + c16 * 16;
        CP_ASYNC16(a_base + SW128(off), src);
    }
    // B: 256 rows x 8 x 16B = 2048 granules, 4 per thread
    #pragma unroll
    for (int i = 0; i < 4; i++) {
        int gr = tid + i * NTHREADS;
        int row = gr >> 3, c16 = gr & 7;
        const __half* src = g_Wh + (size_t)(n0 + row) * K_DIM + k0 + c16 * 8;
        uint32_t off = row * 128 + c16 * 16;
        CP_ASYNC16(b_base + SW128(off), src);
    }
}

__global__ __launch_bounds__(NTHREADS, 1)
void gemm_hmma_kernel(const float* __restrict__ bias, float* __restrict__ out)
{
    extern __shared__ char smem[];
    const uint32_t smem_base = smem_u32(smem);
    const int tid  = threadIdx.x;
    const int wid  = tid >> 5, lane = tid & 31;
    const int wm   = wid & 3;            // 4 warps along M (32 rows each)
    const int wn   = wid >> 2;           // 4 warps along N (64 cols each)
    const int m0   = blockIdx.y * BM;
    const int n0   = blockIdx.x * BN;

    float acc[2][8][4] = {};             // [m-tile 16][n-tile 8][frag]

    // A: row = wm*32 + mt*16 + (lane&15), k-half chunk = (lane>>4)*8 halves
    const int a_row = wm * 32 + (lane & 15);
    const int a_kh  = (lane >> 4) * 8;
    // B x4 covers two n8-tiles: lanes 0-15 -> nt even, 16-31 -> nt odd
    const int b_row = wn * 64 + (lane >> 4) * 8 + (lane & 7);
    const int b_kh  = ((lane >> 3) & 1) * 8;

    #pragma unroll
    for (int s = 0; s < STAGES - 1; s++) { load_stage(smem_base, s, s, m0, n0); CP_COMMIT(); }

    for (int it = 0; it < NITER; it++) {
        const int s = it % STAGES;
        CP_WAIT1();
        __syncthreads();

        const int nxt = it + STAGES - 1;
        if (nxt < NITER) { load_stage(smem_base, nxt % STAGES, nxt, m0, n0); CP_COMMIT(); }

        const uint32_t a_base = smem_base + SM_A(s);
        const uint32_t b_base = smem_base + SM_B(s);

        #pragma unroll
        for (int kk = 0; kk < 4; kk++) {          // 4 x k16 per BK=64
            const int k0 = kk * 16;
            uint32_t af[2][4];
            #pragma unroll
            for (int mt = 0; mt < 2; mt++) {
                uint32_t off = (mt * 16 + a_row) * 128 + (k0 + a_kh) * 2;
                LDSM_X4(af[mt][0], af[mt][1], af[mt][2], af[mt][3],
                        a_base + SW128(off));
            }
            uint32_t bf[8][2];
            #pragma unroll
            for (int p = 0; p < 4; p++) {          // nt pair {2p, 2p+1}
                uint32_t off = (p * 16 + b_row) * 128 + (k0 + b_kh) * 2;
                LDSM_X4(bf[2 * p][0], bf[2 * p][1], bf[2 * p + 1][0], bf[2 * p + 1][1],
                        b_base + SW128(off));
            }
            #pragma unroll
            for (int mt = 0; mt < 2; mt++)
                #pragma unroll
                for (int nt = 0; nt < 8; nt++)
                    MMA16816(acc[mt][nt], af[mt], bf[nt]);
        }
    }

    // epilogue
    const int er = lane >> 2;
    const int ec = (lane & 3) * 2;
    #pragma unroll
    for (int nt = 0; nt < 8; nt++) {
        const int n = n0 + wn * 64 + nt * 8 + ec;
        const float2 bv = *(const float2*)(bias + n);
        #pragma unroll
        for (int mt = 0; mt < 2; mt++) {
            const int m = m0 + wm * 32 + mt * 16 + er;
            float2 v0 = { acc[mt][nt][0] + bv.x, acc[mt][nt][1] + bv.y };
            float2 v1 = { acc[mt][nt][2] + bv.x, acc[mt][nt][3] + bv.y };
            *(float2*)(out + (size_t)m * N_DIM + n)       = v0;
            *(float2*)(out + (size_t)(m + 8) * N_DIM + n) = v1;
        }
    }
}

// ================= launch =================
extern "C" void kernel_launch(void* const* d_in, const int* in_sizes, int n_in,
                              void* d_out, int out_size)
{
    const float* x            = (const float*)d_in[0];
    const int*   nvfp4_idx    = (const int*)d_in[1];
    const float* nvfp4_scales = (const float*)d_in[2];
    const float* nvfp4_gscale = (const float*)d_in[3];
    const float* w_fp8        = (const float*)d_in[4];
    const float* fp8_scale    = (const float*)d_in[5];
    const float* w_fp16       = (const float*)d_in[6];
    const float* bias         = (const float*)d_in[7];
    const void*  inv_perm     = (const void*)d_in[8];
    float*       out          = (float*)d_out;

    cudaFuncSetAttribute(gemm_hmma_kernel, cudaFuncAttributeMaxDynamicSharedMemorySize, SMEM_TOTAL);

    perm_canon_kernel<<<1, 256>>>(inv_perm);
    convert_x_kernel<<<(M_DIM * (size_t)K_DIM) / (256 * 8), 256>>>(x);
    dequant_kernel<<<N_DIM, 256>>>(nvfp4_idx, nvfp4_scales, nvfp4_gscale,
                                   w_fp8, fp8_scale, w_fp16);

    dim3 grid(N_DIM / BN, M_DIM / BM);   // (16, 32)
    gemm_hmma_kernel<<<grid, NTHREADS, SMEM_TOTAL>>>(bias, out);
}